// round 8
// baseline (speedup 1.0000x reference)
#include <cuda_runtime.h>
#include <cstdint>

#define EPS      1e-6f
#define IMG_H    512
#define IMG_W    512
#define PLANES   64            // B*C = 4*16
#define PX       4             // pixels per thread in x
#define TX       (IMG_W / PX)  // 128 threads
#define ROWS_OUT 8             // output rows per thread

#define EXPM     0.60653065971263342f   // exp(-0.5), theta=1
#define EXPM_9   (EXPM / 9.0f)
#define EPS_EXPM (EPS * EXPM)
// contrast = (8/9)*(1 - 2*eps/sd)*EXPM + eps*EXPM, sd = sqrt(vnum/8)
// => oc = fma(K_CON1, rsqrt(vnum), K_CON0)
#define K_CON0   0.53913897f            // (8/9)*EXPM + EPS*EXPM
#define K_CON1   (-3.04984e-6f)         // -2*EPS*sqrt(8)*(8/9)*EXPM
// entropy out = fma(Sp_log2, K_ENT, EPS_EXPM), K_ENT = -ln2*EXPM/9
#define K_ENT    (-0.046712763f)

__device__ __forceinline__ float frsqrt_approx(float a) {
    float r; asm("rsqrt.approx.f32 %0, %1;" : "=f"(r) : "f"(a)); return r;
}
__device__ __forceinline__ float frcp_approx(float a) {
    float r; asm("rcp.approx.f32 %0, %1;" : "=f"(r) : "f"(a)); return r;
}

// Raw load only (no math) so LDGs can be issued far ahead of use.
__device__ __forceinline__ void load_raw(const float* __restrict__ base,
                                         int x0, bool valid, float w[6]) {
    if (valid) {
        const float4 m = *reinterpret_cast<const float4*>(base + x0);
        w[1] = m.x; w[2] = m.y; w[3] = m.z; w[4] = m.w;
        w[0] = (x0 > 0)          ? __ldg(base + x0 - 1)  : 0.0f;
        w[5] = (x0 + PX < IMG_W) ? __ldg(base + x0 + PX) : 0.0f;
    } else {
#pragma unroll
        for (int j = 0; j < 6; ++j) w[j] = 0.0f;
    }
}

// Per-row horizontal triple sums: S1 (values), S2 (squares), Sp (x*log2(x+eps)).
// Computed ONCE per loaded row; reused by the 3 output rows that see this row.
__device__ __forceinline__ void rowstats(const float v[6],
                                         float h1[4], float h2[4], float hp[4]) {
    float sq[6], p[6];
#pragma unroll
    for (int j = 0; j < 6; ++j) {
        sq[j] = v[j] * v[j];
        p[j]  = v[j] * __log2f(v[j] + EPS);
    }
#pragma unroll
    for (int i = 0; i < 4; ++i) {
        h1[i] = (v[i]  + v[i + 1])  + v[i + 2];
        h2[i] = (sq[i] + sq[i + 1]) + sq[i + 2];
        hp[i] = (p[i]  + p[i + 1])  + p[i + 2];
    }
}

__global__ __launch_bounds__(TX, 6)
void texture_martingale_kernel(const float* __restrict__ x,
                               float* __restrict__ out) {
    const int plane = blockIdx.y;                   // 0..63 (b*16+c)
    const int y0    = blockIdx.x * ROWS_OUT;
    const int x0    = threadIdx.x * PX;

    const float* __restrict__ in = x + (size_t)plane * (IMG_H * IMG_W);

    // 3-row rings: raw values + per-row horizontal sums; distance-1 prefetch.
    float v[3][6], h1[3][4], h2[3][4], hp[3][4], nx[6];
    load_raw(in + (y0 - 1) * IMG_W, x0, y0 > 0, v[0]);
    load_raw(in +  y0      * IMG_W, x0, true,   v[1]);
    load_raw(in + (y0 + 1) * IMG_W, x0, true,   nx);   // y0+1 <= 505 always valid
    rowstats(v[0], h1[0], h2[0], hp[0]);
    rowstats(v[1], h1[1], h2[1], hp[1]);

    const float* pnext = in + (y0 + 2) * IMG_W;        // marching prefetch ptr

    const size_t planeSz = (size_t)IMG_H * IMG_W;
    float* __restrict__ o0 = out + (size_t)(4 * plane) * planeSz
                                 + (size_t)y0 * IMG_W + x0;

#pragma unroll
    for (int r = 0; r < ROWS_OUT; ++r) {
        const int sa = r % 3, sb = (r + 1) % 3, sc = (r + 2) % 3;

        // Commit prefetched row; immediately issue next row's LDGs.
#pragma unroll
        for (int j = 0; j < 6; ++j) v[sc][j] = nx[j];
        load_raw(pnext, x0, y0 + r + 2 < IMG_H, nx);
        pnext += IMG_W;

        rowstats(v[sc], h1[sc], h2[sc], hp[sc]);

        float oc[PX], oe[PX], ot[PX], oh[PX];
#pragma unroll
        for (int i = 0; i < PX; ++i) {
            // Vertical sums of per-row horizontal sums (shallow trees).
            const float S1 = (h1[sa][i] + h1[sb][i]) + h1[sc][i];
            const float S2 = (h2[sa][i] + h2[sb][i]) + h2[sc][i];
            const float Sp = (hp[sa][i] + hp[sb][i]) + hp[sc][i];

            const float mean = S1 * (1.0f / 9.0f);
            const float vnum = fmaxf(fmaf(-S1, mean, S2), 1e-12f); // sum (x-mu)^2

            // |x - mean| sum: 9 diffs + balanced abs-add tree (depth 4).
            float e0 = v[sa][i]     - mean, e1 = v[sa][i + 1] - mean,
                  e2 = v[sa][i + 2] - mean, e3 = v[sb][i]     - mean,
                  e4 = v[sb][i + 1] - mean, e5 = v[sb][i + 2] - mean,
                  e6 = v[sc][i]     - mean, e7 = v[sc][i + 1] - mean,
                  e8 = v[sc][i + 2] - mean;
            const float s01 = fabsf(e0) + fabsf(e1);
            const float s23 = fabsf(e2) + fabsf(e3);
            const float s45 = fabsf(e4) + fabsf(e5);
            const float s67 = fabsf(e6) + fabsf(e7);
            const float sab = ((s01 + s23) + (s45 + s67)) + fabsf(e8);

            const float hom = frcp_approx(fmaf(sab, 1.0f / 9.0f, 1.0f));

            oc[i] = fmaf(K_CON1, frsqrt_approx(vnum), K_CON0);  // contrast
            oe[i] = fmaf(S2,  EXPM_9, EPS_EXPM);                // energy
            ot[i] = fmaf(Sp,  K_ENT,  EPS_EXPM);                // entropy
            oh[i] = fmaf(hom, EXPM,   EPS_EXPM);                // homogeneity
        }

        // Streaming stores: output is write-once; preserve L2 for input reuse.
        __stcs(reinterpret_cast<float4*>(o0),
               make_float4(oc[0], oc[1], oc[2], oc[3]));
        __stcs(reinterpret_cast<float4*>(o0 + planeSz),
               make_float4(oe[0], oe[1], oe[2], oe[3]));
        __stcs(reinterpret_cast<float4*>(o0 + 2 * planeSz),
               make_float4(ot[0], ot[1], ot[2], ot[3]));
        __stcs(reinterpret_cast<float4*>(o0 + 3 * planeSz),
               make_float4(oh[0], oh[1], oh[2], oh[3]));
        o0 += IMG_W;
    }
}

extern "C" void kernel_launch(void* const* d_in, const int* in_sizes, int n_in,
                              void* d_out, int out_size) {
    const float* x = (const float*)d_in[0];
    float* out = (float*)d_out;

    dim3 block(TX, 1);
    dim3 grid(IMG_H / ROWS_OUT, PLANES);
    texture_martingale_kernel<<<grid, block>>>(x, out);
}